// round 3
// baseline (speedup 1.0000x reference)
#include <cuda_runtime.h>
#include <cstdint>

#define GAIN   1.6778523489932886f   /* 1/0.596 */
#define INV058 1.3130643285972254f   /* 1/sqrt(0.7^2+0.3^2) */
#define EPSN   1e-4f

/* ---------------- static device scratch (no allocations allowed) -------- */
__device__ __align__(16) float g_wpool[15230976];
__device__ __align__(16) float g_pm[4];
__device__ __align__(16) float g_xn[33554432];
__device__ __align__(16) float g_bufA[67108864];
__device__ __align__(16) float g_bufB[67108864];
__device__ __align__(16) float g_h[33554432];
__device__ __align__(16) float g_pool[8388608];
__device__ __align__(16) float g_x[16777216];

/* weight pool offsets (floats), all 16B aligned */
#define O_C0W1 0
#define O_C0WD 8192
#define O_C0W2 10112
#define O_C0DN 18304
#define O_C1W1 26496
#define O_C1WD 59264
#define O_C1W2 63104
#define O_C1DN 95872
#define O_C2W1 128640
#define O_C2WD 259712
#define O_C2W2 267392
#define O_C2DN 398464
#define O_HG   529536
#define O_DW   4723840
#define O_GRU  4736128
#define O_OUT  13124736

__device__ __forceinline__ float sigmoidf_fast(float x) {
    return __fdividef(1.f, 1.f + __expf(-x));
}
__device__ __forceinline__ float mp_siluf(float x) {
    return x * sigmoidf_fast(x) * GAIN;
}

/* ---------------- weight normalization (per output-channel row) --------- */
__global__ void norm_rows(const float* __restrict__ src, float* __restrict__ dst, int rowlen) {
    int r = blockIdx.x;
    const float* s = src + (long long)r * rowlen;
    float* d = dst + (long long)r * rowlen;
    float acc = 0.f;
    for (int i = threadIdx.x; i < rowlen; i += blockDim.x) { float v = s[i]; acc = fmaf(v, v, acc); }
#pragma unroll
    for (int off = 16; off; off >>= 1) acc += __shfl_down_sync(0xffffffffu, acc, off);
    __shared__ float sm[32];
    int warp = threadIdx.x >> 5, lane = threadIdx.x & 31;
    if (lane == 0) sm[warp] = acc;
    __syncthreads();
    if (threadIdx.x == 0) {
        float t = 0.f;
        int nw = blockDim.x >> 5;
        for (int i = 0; i < nw; i++) t += sm[i];
        sm[0] = rsqrtf(t + 1e-8f);
    }
    __syncthreads();
    float iv = sm[0];
    for (int i = threadIdx.x; i < rowlen; i += blockDim.x) d[i] = s[i] * iv;
}

/* ---------------- proj closed-form pixel norm --------------------------- */
__global__ void proj_moments(const float* __restrict__ pw, const float* __restrict__ pb,
                             float* __restrict__ pm) {
    if (threadIdx.x == 0) {
        float a = 0.f, b2 = 0.f, c2 = 0.f;
        for (int i = 0; i < 64; i++) {
            float w = pw[i], bb = pb[i];
            a = fmaf(w, w, a); b2 = fmaf(w, bb, b2); c2 = fmaf(bb, bb, c2);
        }
        pm[0] = a * (1.f / 64.f); pm[1] = b2 * (1.f / 64.f); pm[2] = c2 * (1.f / 64.f);
    }
}

/* x = proj(audio); pixel_norm has closed form in A -> write normed tensor  */
__global__ void proj_pixelnorm(const float* __restrict__ audio, const float* __restrict__ pw,
                               const float* __restrict__ pb, const float* __restrict__ pm,
                               float* __restrict__ xn) {
    long long p = (long long)blockIdx.x * blockDim.x + threadIdx.x;
    if (p >= 524288LL) return;
    float A = audio[p];
    float ms = fmaf(A * A, pm[0], fmaf(2.f * A, pm[1], pm[2]));
    float iv = rsqrtf(ms + EPSN);
    long long b = p >> 18;
    long long rem = p & 262143LL;
    float* o = xn + b * 64LL * 262144LL + rem;
    float pwc, pbc;
#pragma unroll
    for (int c = 0; c < 64; c++) {
        pwc = pw[c]; pbc = pb[c];
        o[(long long)c * 262144LL] = fmaf(A, pwc, pbc) * iv;
    }
}

/* ---------------- generic pixel norm (thread per position) -------------- */
__global__ void pixelnorm(const float* __restrict__ x, float* __restrict__ xn,
                          int C, long long P, long long BP) {
    long long p = (long long)blockIdx.x * blockDim.x + threadIdx.x;
    if (p >= BP) return;
    long long b = p / P, pp = p % P;
    const float* xi = x + b * (long long)C * P + pp;
    float s = 0.f;
#pragma unroll 8
    for (int c = 0; c < C; c++) { float v = xi[(long long)c * P]; s = fmaf(v, v, s); }
    float iv = rsqrtf(s / (float)C + EPSN);
    float* o = xn + b * (long long)C * P + pp;
#pragma unroll 8
    for (int c = 0; c < C; c++) o[(long long)c * P] = xi[(long long)c * P] * iv;
}

/* ---------------- tiled fp32 GEMM: Y[M,P] = W[M,K] @ X[K,P] ------------- */
/* M%64==0, K%16==0, P%64==0. grid = (P/64, M/64, B), 256 threads          */
template <bool SILU_LOAD, bool MPADD>
__global__ void __launch_bounds__(256) gemm64(const float* __restrict__ W,
                                              const float* __restrict__ X,
                                              float* __restrict__ Y,
                                              const float* __restrict__ R,
                                              int M, int K, long long P) {
    __shared__ __align__(16) float Ws[16][68];
    __shared__ __align__(16) float Xs[16][68];
    const int tid = threadIdx.x;
    const long long p0 = (long long)blockIdx.x * 64;
    const int m0 = blockIdx.y * 64;
    const int b = blockIdx.z;
    const float* Xb = X + (long long)b * K * P;
    float* Yb = Y + (long long)b * M * P;
    const float* Rb = MPADD ? (R + (long long)b * M * P) : (const float*)0;

    const int wm = tid >> 2;
    const int wk = (tid & 3) << 2;
    const int xk = tid >> 4;
    const int xp = (tid & 15) << 2;
    const int row0 = (tid >> 4) << 2;
    const int col0 = (tid & 15) << 2;

    float acc[4][4];
#pragma unroll
    for (int i = 0; i < 4; i++)
#pragma unroll
        for (int j = 0; j < 4; j++) acc[i][j] = 0.f;

    for (int k0 = 0; k0 < K; k0 += 16) {
        float4 w4 = *(const float4*)(W + (long long)(m0 + wm) * K + (k0 + wk));
        Ws[wk + 0][wm] = w4.x; Ws[wk + 1][wm] = w4.y;
        Ws[wk + 2][wm] = w4.z; Ws[wk + 3][wm] = w4.w;
        float4 x4 = *(const float4*)(Xb + (long long)(k0 + xk) * P + (p0 + xp));
        if (SILU_LOAD) {
            x4.x = mp_siluf(x4.x); x4.y = mp_siluf(x4.y);
            x4.z = mp_siluf(x4.z); x4.w = mp_siluf(x4.w);
        }
        *(float4*)(&Xs[xk][xp]) = x4;
        __syncthreads();
#pragma unroll
        for (int kk = 0; kk < 16; kk++) {
            const float4 av = *(const float4*)(&Ws[kk][row0]);
            const float4 bv = *(const float4*)(&Xs[kk][col0]);
            acc[0][0] = fmaf(av.x, bv.x, acc[0][0]);
            acc[0][1] = fmaf(av.x, bv.y, acc[0][1]);
            acc[0][2] = fmaf(av.x, bv.z, acc[0][2]);
            acc[0][3] = fmaf(av.x, bv.w, acc[0][3]);
            acc[1][0] = fmaf(av.y, bv.x, acc[1][0]);
            acc[1][1] = fmaf(av.y, bv.y, acc[1][1]);
            acc[1][2] = fmaf(av.y, bv.z, acc[1][2]);
            acc[1][3] = fmaf(av.y, bv.w, acc[1][3]);
            acc[2][0] = fmaf(av.z, bv.x, acc[2][0]);
            acc[2][1] = fmaf(av.z, bv.y, acc[2][1]);
            acc[2][2] = fmaf(av.z, bv.z, acc[2][2]);
            acc[2][3] = fmaf(av.z, bv.w, acc[2][3]);
            acc[3][0] = fmaf(av.w, bv.x, acc[3][0]);
            acc[3][1] = fmaf(av.w, bv.y, acc[3][1]);
            acc[3][2] = fmaf(av.w, bv.z, acc[3][2]);
            acc[3][3] = fmaf(av.w, bv.w, acc[3][3]);
        }
        __syncthreads();
    }
#pragma unroll
    for (int i = 0; i < 4; i++) {
        long long base = (long long)(m0 + row0 + i) * P + p0 + col0;
        float4 o = make_float4(acc[i][0], acc[i][1], acc[i][2], acc[i][3]);
        if (MPADD) {
            float4 r4 = *(const float4*)(Rb + base);
            o.x = fmaf(0.7f, r4.x, 0.3f * o.x) * INV058;
            o.y = fmaf(0.7f, r4.y, 0.3f * o.y) * INV058;
            o.z = fmaf(0.7f, r4.z, 0.3f * o.z) * INV058;
            o.w = fmaf(0.7f, r4.w, 0.3f * o.w) * INV058;
        }
        *(float4*)(Yb + base) = o;
    }
}

/* ---------------- depthwise 5x3 conv2d (pad 2,1), silu at output -------- */
__global__ void dwconv2d_silu(const float* __restrict__ in, const float* __restrict__ w,
                              float* __restrict__ out, int C, int F, long long total) {
    long long t = (long long)blockIdx.x * blockDim.x + threadIdx.x;
    if (t >= total) return;
    int l0 = (int)(t & 511) << 2;
    long long r = t >> 9;
    int f = (int)(r % F); r /= F;
    int c = (int)(r % C);
    int b = (int)(r / C);
    const float* base = in + ((long long)(b * C + c)) * F * 2048LL;
    const float* wc = w + c * 15;
    float a0 = 0.f, a1 = 0.f, a2 = 0.f, a3 = 0.f;
#pragma unroll
    for (int df = 0; df < 5; df++) {
        int ff = f + df - 2;
        if (ff < 0 || ff >= F) continue;
        const float* row = base + (long long)ff * 2048;
        float v[6];
#pragma unroll
        for (int j = 0; j < 6; j++) {
            int ll = l0 + j - 1;
            v[j] = (ll >= 0 && ll < 2048) ? row[ll] : 0.f;
        }
#pragma unroll
        for (int dl = 0; dl < 3; dl++) {
            float wv = wc[df * 3 + dl];
            a0 = fmaf(wv, v[dl + 0], a0);
            a1 = fmaf(wv, v[dl + 1], a1);
            a2 = fmaf(wv, v[dl + 2], a2);
            a3 = fmaf(wv, v[dl + 3], a3);
        }
    }
    float* o = out + (((long long)(b * C + c)) * F + f) * 2048LL + l0;
    o[0] = mp_siluf(a0); o[1] = mp_siluf(a1);
    o[2] = mp_siluf(a2); o[3] = mp_siluf(a3);
}

/* ---------------- freq average pool ------------------------------------ */
__global__ void avgpool_f(const float* __restrict__ in, float* __restrict__ out,
                          int C, int F, int Fo, int s, long long total) {
    long long t = (long long)blockIdx.x * blockDim.x + threadIdx.x;
    if (t >= total) return;
    int l = (int)(t & 2047);
    long long r = t >> 11;
    int fo = (int)(r % Fo); r /= Fo;
    int c = (int)(r % C);
    int b = (int)(r / C);
    const float* p = in + (((long long)(b * C + c)) * F + fo * s) * 2048LL + l;
    float sum = 0.f;
    for (int j = 0; j < s; j++) sum += p[(long long)j * 2048];
    out[t] = sum * (1.f / (float)s);
}

/* ---------------- seq: silu -> depthwise k3 -> silu --------------------- */
__global__ void dwconv1d_silu(const float* __restrict__ hg, const float* __restrict__ w,
                              float* __restrict__ out) {
    long long t = (long long)blockIdx.x * blockDim.x + threadIdx.x;
    if (t >= 1048576LL) return;
    int l0 = (int)(t & 511) << 2;
    int c = (int)((t >> 9) & 1023);
    int b = (int)(t >> 19);
    const float* row = hg + ((long long)b * 2048 + c) * 2048LL;
    const float* wc = w + c * 3;
    float v[6];
#pragma unroll
    for (int j = 0; j < 6; j++) {
        int ll = l0 + j - 1;
        v[j] = (ll >= 0 && ll < 2048) ? mp_siluf(row[ll]) : 0.f;
    }
    float a0 = 0.f, a1 = 0.f, a2 = 0.f, a3 = 0.f;
#pragma unroll
    for (int dl = 0; dl < 3; dl++) {
        float wv = wc[dl];
        a0 = fmaf(wv, v[dl + 0], a0);
        a1 = fmaf(wv, v[dl + 1], a1);
        a2 = fmaf(wv, v[dl + 2], a2);
        a3 = fmaf(wv, v[dl + 3], a3);
    }
    float* o = out + ((long long)b * 1024 + c) * 2048LL + l0;
    o[0] = mp_siluf(a0); o[1] = mp_siluf(a1);
    o[2] = mp_siluf(a2); o[3] = mp_siluf(a3);
}

/* ---------------- minGRU warp scan fused with output gate --------------- */
__global__ void gru_scan(const float* __restrict__ u, const float* __restrict__ hg,
                         float* __restrict__ out) {
    int w = (int)((blockIdx.x * blockDim.x + threadIdx.x) >> 5);
    int lane = threadIdx.x & 31;
    if (w >= 2048) return;
    int bt = w >> 10, c = w & 1023;
    const float* zrow = u + ((long long)bt * 2048 + c) * 2048LL;
    const float* crow = zrow + 1024LL * 2048LL;
    const float* grow = hg + ((long long)bt * 2048 + 1024 + c) * 2048LL;
    float* orow = out + ((long long)bt * 1024 + c) * 2048LL;
    float carry = 0.f;
    for (int l0 = 0; l0 < 2048; l0 += 32) {
        float z = sigmoidf_fast(zrow[l0 + lane]);
        float a = 1.f - z;
        float bb = z * crow[l0 + lane];
#pragma unroll
        for (int off = 1; off < 32; off <<= 1) {
            float ap = __shfl_up_sync(0xffffffffu, a, off);
            float bp = __shfl_up_sync(0xffffffffu, bb, off);
            if (lane >= off) { bb = fmaf(a, bp, bb); a *= ap; }
        }
        float ov = fmaf(a, carry, bb);
        carry = __shfl_sync(0xffffffffu, ov, 31);
        orow[l0 + lane] = ov * mp_siluf(grow[l0 + lane]);
    }
}

/* ---------------- final activation -------------------------------------- */
__global__ void silu_out(const float* __restrict__ in, float* __restrict__ out, long long n) {
    long long i = (long long)blockIdx.x * blockDim.x + threadIdx.x;
    if (i < n) out[i] = mp_siluf(in[i]);
}

/* ======================================================================== */
extern "C" void kernel_launch(void* const* d_in, const int* in_sizes, int n_in,
                              void* d_out, int out_size) {
    const float* audio = (const float*)d_in[0];
    const float* pw    = (const float*)d_in[1];
    const float* pb    = (const float*)d_in[2];
    const float* c0w1  = (const float*)d_in[3];
    const float* c0wd  = (const float*)d_in[4];
    const float* c0w2  = (const float*)d_in[5];
    const float* c0dn  = (const float*)d_in[6];
    const float* c1w1  = (const float*)d_in[7];
    const float* c1wd  = (const float*)d_in[8];
    const float* c1w2  = (const float*)d_in[9];
    const float* c1dn  = (const float*)d_in[10];
    const float* c2w1  = (const float*)d_in[11];
    const float* c2wd  = (const float*)d_in[12];
    const float* c2w2  = (const float*)d_in[13];
    const float* c2dn  = (const float*)d_in[14];
    const float* hgw   = (const float*)d_in[15];
    const float* dww   = (const float*)d_in[16];
    const float* gruw  = (const float*)d_in[17];
    const float* outw  = (const float*)d_in[18];

    float *wp, *pm, *xn, *bufA, *bufB, *hb, *pool, *xb;
    cudaGetSymbolAddress((void**)&wp,   g_wpool);
    cudaGetSymbolAddress((void**)&pm,   g_pm);
    cudaGetSymbolAddress((void**)&xn,   g_xn);
    cudaGetSymbolAddress((void**)&bufA, g_bufA);
    cudaGetSymbolAddress((void**)&bufB, g_bufB);
    cudaGetSymbolAddress((void**)&hb,   g_h);
    cudaGetSymbolAddress((void**)&pool, g_pool);
    cudaGetSymbolAddress((void**)&xb,   g_x);

    /* weight normalization */
    norm_rows<<<128, 128>>>(c0w1, wp + O_C0W1, 64);
    norm_rows<<<128, 128>>>(c0wd, wp + O_C0WD, 15);
    norm_rows<<<64, 128>>>(c0w2, wp + O_C0W2, 128);
    norm_rows<<<128, 128>>>(c0dn, wp + O_C0DN, 64);
    norm_rows<<<256, 128>>>(c1w1, wp + O_C1W1, 128);
    norm_rows<<<256, 128>>>(c1wd, wp + O_C1WD, 15);
    norm_rows<<<128, 128>>>(c1w2, wp + O_C1W2, 256);
    norm_rows<<<256, 128>>>(c1dn, wp + O_C1DN, 128);
    norm_rows<<<512, 128>>>(c2w1, wp + O_C2W1, 256);
    norm_rows<<<512, 128>>>(c2wd, wp + O_C2WD, 15);
    norm_rows<<<256, 128>>>(c2w2, wp + O_C2W2, 512);
    norm_rows<<<512, 128>>>(c2dn, wp + O_C2DN, 256);
    norm_rows<<<8192, 128>>>(hgw, wp + O_HG, 512);
    norm_rows<<<4096, 128>>>(dww, wp + O_DW, 3);
    norm_rows<<<8192, 128>>>(gruw, wp + O_GRU, 1024);
    norm_rows<<<2048, 128>>>(outw, wp + O_OUT, 1024);

    /* block 0  (C 64->128->64->pool4->128, F=128, P=262144) */
    proj_moments<<<1, 32>>>(pw, pb, pm);
    proj_pixelnorm<<<2048, 256>>>(audio, pw, pb, pm, xn);
    gemm64<true, false><<<dim3(4096, 2, 2), 256>>>(wp + O_C0W1, xn, bufA, (const float*)0, 128, 64, 262144LL);
    dwconv2d_silu<<<65536, 256>>>(bufA, wp + O_C0WD, bufB, 128, 128, 16777216LL);
    gemm64<false, true><<<dim3(4096, 1, 2), 256>>>(wp + O_C0W2, bufB, hb, xn, 64, 128, 262144LL);
    avgpool_f<<<32768, 256>>>(hb, pool, 64, 128, 32, 4, 8388608LL);
    gemm64<false, false><<<dim3(1024, 2, 2), 256>>>(wp + O_C0DN, pool, xb, (const float*)0, 128, 64, 65536LL);

    /* block 1  (C 128->256->128->pool4->256, F=32, P=65536) */
    pixelnorm<<<512, 256>>>(xb, xn, 128, 65536LL, 131072LL);
    gemm64<true, false><<<dim3(1024, 4, 2), 256>>>(wp + O_C1W1, xn, bufA, (const float*)0, 256, 128, 65536LL);
    dwconv2d_silu<<<32768, 256>>>(bufA, wp + O_C1WD, bufB, 256, 32, 8388608LL);
    gemm64<false, true><<<dim3(1024, 2, 2), 256>>>(wp + O_C1W2, bufB, hb, xn, 128, 256, 65536LL);
    avgpool_f<<<16384, 256>>>(hb, pool, 128, 32, 8, 4, 4194304LL);
    gemm64<false, false><<<dim3(256, 4, 2), 256>>>(wp + O_C1DN, pool, xb, (const float*)0, 256, 128, 16384LL);

    /* block 2  (C 256->512->256->pool8->512, F=8, P=16384) */
    pixelnorm<<<128, 256>>>(xb, xn, 256, 16384LL, 32768LL);
    gemm64<true, false><<<dim3(256, 8, 2), 256>>>(wp + O_C2W1, xn, bufA, (const float*)0, 512, 256, 16384LL);
    dwconv2d_silu<<<16384, 256>>>(bufA, wp + O_C2WD, bufB, 512, 8, 4194304LL);
    gemm64<false, true><<<dim3(256, 4, 2), 256>>>(wp + O_C2W2, bufB, hb, xn, 256, 512, 16384LL);
    avgpool_f<<<4096, 256>>>(hb, pool, 256, 8, 1, 8, 1048576LL);
    gemm64<false, false><<<dim3(32, 8, 2), 256>>>(wp + O_C2DN, pool, xb, (const float*)0, 512, 256, 2048LL);

    /* seq blocks ×4  (C=512, L=2048) */
    for (int i = 0; i < 4; i++) {
        pixelnorm<<<16, 256>>>(xb, xn, 512, 2048LL, 4096LL);
        gemm64<false, false><<<dim3(32, 32, 2), 256>>>(wp + O_HG + i * 1048576, xn, bufA, (const float*)0, 2048, 512, 2048LL);
        dwconv1d_silu<<<4096, 256>>>(bufA, wp + O_DW + i * 3072, bufB);
        gemm64<false, false><<<dim3(32, 32, 2), 256>>>(wp + O_GRU + i * 2097152, bufB, hb, (const float*)0, 2048, 1024, 2048LL);
        gru_scan<<<256, 256>>>(hb, bufA, pool);
        gemm64<false, true><<<dim3(32, 8, 2), 256>>>(wp + O_OUT + i * 524288, pool, xb, xn, 512, 1024, 2048LL);
    }

    silu_out<<<8192, 256>>>(xb, (float*)d_out, 2097152LL);
}